// round 10
// baseline (speedup 1.0000x reference)
#include <cuda_runtime.h>
#include <cuda_bf16.h>
#include <math.h>
#include <stdint.h>

#define B_    2
#define S_    2048
#define H_    16
#define D_    64
#define HID   1024
#define QKV_  1024
#define M_TOK 4096
#define N_QKV 3072
#define SCALE 0.125f

typedef unsigned long long u64;
typedef __nv_bfloat16 bf16;

// ---------------- helpers ----------------------------------------------------
__device__ __forceinline__ uint32_t pkbf(bf16 x, bf16 y) {
    __nv_bfloat162 t; t.x = x; t.y = y;
    return *(uint32_t*)&t;
}
__device__ __forceinline__ uint32_t splitp(float x, float y, uint32_t& lo) {
    bf16 hx = __float2bfloat16(x), hy = __float2bfloat16(y);
    bf16 lx = __float2bfloat16(x - __bfloat162float(hx));
    bf16 ly = __float2bfloat16(y - __bfloat162float(hy));
    lo = pkbf(lx, ly);
    return pkbf(hx, hy);
}
__device__ __forceinline__ void mma16816(float* d,
    uint32_t a0, uint32_t a1, uint32_t a2, uint32_t a3, uint32_t b0, uint32_t b1) {
    asm volatile(
        "mma.sync.aligned.m16n8k16.row.col.f32.bf16.bf16.f32 "
        "{%0,%1,%2,%3},{%4,%5,%6,%7},{%8,%9},{%0,%1,%2,%3};"
        : "+f"(d[0]), "+f"(d[1]), "+f"(d[2]), "+f"(d[3])
        : "r"(a0), "r"(a1), "r"(a2), "r"(a3), "r"(b0), "r"(b1));
}
__device__ __forceinline__ void ldsm4(uint32_t* r, uint32_t addr) {
    asm volatile("ldmatrix.sync.aligned.m8n8.x4.shared.b16 {%0,%1,%2,%3},[%4];"
                 : "=r"(r[0]), "=r"(r[1]), "=r"(r[2]), "=r"(r[3]) : "r"(addr));
}
__device__ __forceinline__ uint32_t smem_u32(const void* p) {
    uint32_t a;
    asm("{ .reg .u64 t; cvta.to.shared.u64 t, %1; cvt.u32.u64 %0, t; }" : "=r"(a) : "l"(p));
    return a;
}
__device__ __forceinline__ void bulkcp(uint32_t dst, const void* src,
                                       uint32_t bytes, uint32_t mbar) {
    asm volatile(
        "cp.async.bulk.shared::cluster.global.mbarrier::complete_tx::bytes "
        "[%0], [%1], %2, [%3];"
        :: "r"(dst), "l"(src), "r"(bytes), "r"(mbar) : "memory");
}
#define MBAR_INIT(a, c) \
    asm volatile("mbarrier.init.shared.b64 [%0], %1;" :: "r"(a), "r"(c) : "memory")
#define MBAR_EXPECT(a, bytes) \
    asm volatile("mbarrier.arrive.expect_tx.shared.b64 _, [%0], %1;" \
                 :: "r"(a), "r"(bytes) : "memory")
#define MBAR_WAIT(a, ph) do {                                                  \
    uint32_t _m = (a); uint32_t _p = (ph); uint32_t _done;                     \
    asm volatile("{ .reg .pred p; mbarrier.try_wait.parity.acquire.cta.shared::cta.b64 p, [%1], %2;" \
                 " selp.b32 %0,1,0,p; }" : "=r"(_done) : "r"(_m), "r"(_p) : "memory"); \
    if (!_done) {                                                              \
        asm volatile("{ .reg .pred P1; WL_%=:"                                 \
                     " mbarrier.try_wait.parity.acquire.cta.shared::cta.b64 P1, [%0], %1, 0x989680;" \
                     " @P1 bra.uni WD_%=; bra.uni WL_%=; WD_%=: }"             \
                     :: "r"(_m), "r"(_p) : "memory");                          \
    }                                                                          \
} while (0)

// ---------------- tiled layout constants -------------------------------------
#define GLD2 40
#define APIECE (128 * GLD2)
#define AQLD 72
#define KPIECE (128 * AQLD)
#define AVLD 136
#define VPIECE (64 * AVLD)

// ---------------- scratch ----------------------------------------------------
__device__ float g_qkv[(size_t)M_TOK * N_QKV];
__device__ bf16 g_xh[(size_t)32 * 32 * APIECE],  g_xl[(size_t)32 * 32 * APIECE];
__device__ bf16 g_wqh[(size_t)24 * 32 * APIECE], g_wql[(size_t)24 * 32 * APIECE];
__device__ bf16 g_woh[(size_t)8 * 32 * APIECE],  g_wol[(size_t)8 * 32 * APIECE];
__device__ bf16 g_ath[(size_t)32 * 32 * APIECE], g_atl[(size_t)32 * 32 * APIECE];
__device__ bf16 g_kh[(size_t)512 * KPIECE],      g_kl[(size_t)512 * KPIECE];
__device__ bf16 g_vh[(size_t)512 * VPIECE],      g_vl[(size_t)512 * VPIECE];

// ---------------------------------------------------------------------------
// split pre-passes
// ---------------------------------------------------------------------------
__global__ __launch_bounds__(256) void split_tiled(
    const float* __restrict__ src, bf16* __restrict__ h, bf16* __restrict__ l, int C)
{
    const size_t e = ((size_t)blockIdx.x * 256 + threadIdx.x) * 8;
    const int r = (int)(e / C), c = (int)(e % C);
    float4 a = *(const float4*)(src + e);
    float4 b = *(const float4*)(src + e + 4);
    uint32_t l0, l1, l2, l3;
    uint32_t h0 = splitp(a.x, a.y, l0);
    uint32_t h1 = splitp(a.z, a.w, l1);
    uint32_t h2 = splitp(b.x, b.y, l2);
    uint32_t h3 = splitp(b.z, b.w, l3);
    const size_t dst = ((size_t)((r >> 7) * (C >> 5) + (c >> 5))) * APIECE
                     + (size_t)(r & 127) * GLD2 + (c & 31);
    *(uint4*)(h + dst) = make_uint4(h0, h1, h2, h3);
    *(uint4*)(l + dst) = make_uint4(l0, l1, l2, l3);
}

__global__ __launch_bounds__(256) void split_vt(
    const float* __restrict__ qkv, bf16* __restrict__ vh, bf16* __restrict__ vl)
{
    __shared__ float T[64][65];
    const int st = blockIdx.x;
    const int bh = blockIdx.y;
    const int b = bh >> 4, h = bh & 15;
    const int s0 = st * 64;
    const int tid = threadIdx.x;
    {
        const int sl = tid >> 2;
        const int cq = tid & 3;
        const float* src = qkv + ((size_t)(b * S_ + s0 + sl)) * N_QKV
                         + 2 * QKV_ + h * D_ + cq * 16;
#pragma unroll
        for (int j = 0; j < 4; j++) {
            float4 v = *(const float4*)(src + j * 4);
            T[cq * 16 + j * 4 + 0][sl] = v.x;
            T[cq * 16 + j * 4 + 1][sl] = v.y;
            T[cq * 16 + j * 4 + 2][sl] = v.z;
            T[cq * 16 + j * 4 + 3][sl] = v.w;
        }
    }
    __syncthreads();
    const int d = tid >> 2;
    const int sq = tid & 3;
    uint32_t hh[8], ll[8];
#pragma unroll
    for (int k = 0; k < 8; k++)
        hh[k] = splitp(T[d][sq * 16 + 2 * k], T[d][sq * 16 + 2 * k + 1], ll[k]);
    const size_t dst = (size_t)(bh * 16 + (st >> 1)) * VPIECE
                     + (size_t)d * AVLD + (st & 1) * 64 + sq * 16;
    *(uint4*)(vh + dst)     = make_uint4(hh[0], hh[1], hh[2], hh[3]);
    *(uint4*)(vh + dst + 8) = make_uint4(hh[4], hh[5], hh[6], hh[7]);
    *(uint4*)(vl + dst)     = make_uint4(ll[0], ll[1], ll[2], ll[3]);
    *(uint4*)(vl + dst + 8) = make_uint4(ll[4], ll[5], ll[6], ll[7]);
}

// ---------------------------------------------------------------------------
// Tensor-core NT GEMM: bulk-copy pipeline, term-major MMA order (distance 8)
// ---------------------------------------------------------------------------
#define GT_B (128 * GLD2 * 2)
#define GST_B (4 * GT_B)
#define GEMM_SMEM (2 * GST_B + 16)

__global__ __launch_bounds__(256, 2) void gemm_bf(
    const bf16* __restrict__ Ah, const bf16* __restrict__ Al,
    const bf16* __restrict__ Bh, const bf16* __restrict__ Bl,
    const float* __restrict__ bias, float* __restrict__ C,
    bf16* __restrict__ kh, bf16* __restrict__ kl,
    int M, int N, int K, int kmode)
{
    extern __shared__ char smem[];
    const uint32_t sb = smem_u32(smem);
    const uint32_t mbar = sb + 2 * GST_B;

    const int tid = threadIdx.x;
    const int wid = tid >> 5;
    const int lid = tid & 31;
    const int g   = lid >> 2;
    const int tg  = lid & 3;
    const int wm  = (wid & 1) * 64;
    const int wn  = (wid >> 1) * 32;
    const int bm  = blockIdx.y * 128;
    const int bn  = blockIdx.x * 128;

    const int kp = K >> 5;
    const bf16* pAh = Ah + (size_t)blockIdx.y * kp * APIECE;
    const bf16* pAl = Al + (size_t)blockIdx.y * kp * APIECE;
    const bf16* pBh = Bh + (size_t)blockIdx.x * kp * APIECE;
    const bf16* pBl = Bl + (size_t)blockIdx.x * kp * APIECE;

    if (tid == 0) {
        MBAR_INIT(mbar, 1);
        MBAR_INIT(mbar + 8, 1);
    }
    __syncthreads();

    auto issue = [&](int buf, int c) {
        const uint32_t mb = mbar + buf * 8;
        const uint32_t d  = sb + buf * GST_B;
        MBAR_EXPECT(mb, GST_B);
        bulkcp(d,            pAh + (size_t)c * APIECE, GT_B, mb);
        bulkcp(d + GT_B,     pAl + (size_t)c * APIECE, GT_B, mb);
        bulkcp(d + 2 * GT_B, pBh + (size_t)c * APIECE, GT_B, mb);
        bulkcp(d + 3 * GT_B, pBl + (size_t)c * APIECE, GT_B, mb);
    };

    if (tid == 0) { issue(0, 0); issue(1, 1); }

    const uint32_t aLane = (uint32_t)((lid & 15) * GLD2 + ((lid >> 4) << 3)) * 2;
    const uint32_t bLane = (uint32_t)((wn + lid) * GLD2) * 2;

    float acc[4][4][4];
#pragma unroll
    for (int mi = 0; mi < 4; mi++)
#pragma unroll
        for (int ni = 0; ni < 4; ni++)
#pragma unroll
            for (int r = 0; r < 4; r++) acc[mi][ni][r] = 0.f;

    int ph0 = 0, ph1 = 0;
    for (int c = 0; c < kp; c++) {
        const int buf = c & 1;
        if (buf == 0) { MBAR_WAIT(mbar, ph0); ph0 ^= 1; }
        else          { MBAR_WAIT(mbar + 8, ph1); ph1 ^= 1; }

        const uint32_t sAH = sb + buf * GST_B;
        const uint32_t sAL = sAH + GT_B;
        const uint32_t sBH = sAH + 2 * GT_B;
        const uint32_t sBL = sAH + 3 * GT_B;

#pragma unroll
        for (int k2 = 0; k2 < 2; k2++) {
            const uint32_t kOff = k2 * 32;
            uint32_t bh0[4], bh1[4], bl0[4], bl1[4];
            ldsm4(bh0, sBH + bLane + kOff);
            ldsm4(bh1, sBH + bLane + kOff + 16);
            ldsm4(bl0, sBL + bLane + kOff);
            ldsm4(bl1, sBL + bLane + kOff + 16);
#pragma unroll
            for (int mp = 0; mp < 2; mp++) {
                uint32_t ah[2][4], al[2][4];
#pragma unroll
                for (int m2 = 0; m2 < 2; m2++) {
                    const uint32_t rOff =
                        (uint32_t)(wm + (mp * 2 + m2) * 16) * 80 + aLane + kOff;
                    ldsm4(ah[m2], sAH + rOff);
                    ldsm4(al[m2], sAL + rOff);
                }
                // term hh: distance 8 between same-acc MMAs
#pragma unroll
                for (int m2 = 0; m2 < 2; m2++)
#pragma unroll
                    for (int ni = 0; ni < 4; ni++)
                        mma16816(acc[mp * 2 + m2][ni], ah[m2][0], ah[m2][1],
                                 ah[m2][2], ah[m2][3], bh0[ni], bh1[ni]);
                // term hl
#pragma unroll
                for (int m2 = 0; m2 < 2; m2++)
#pragma unroll
                    for (int ni = 0; ni < 4; ni++)
                        mma16816(acc[mp * 2 + m2][ni], ah[m2][0], ah[m2][1],
                                 ah[m2][2], ah[m2][3], bl0[ni], bl1[ni]);
                // term lh
#pragma unroll
                for (int m2 = 0; m2 < 2; m2++)
#pragma unroll
                    for (int ni = 0; ni < 4; ni++)
                        mma16816(acc[mp * 2 + m2][ni], al[m2][0], al[m2][1],
                                 al[m2][2], al[m2][3], bh0[ni], bh1[ni]);
            }
        }
        __syncthreads();
        if (tid == 0 && c + 2 < kp) issue(buf, c + 2);
    }

    const bool ksplit = kmode && (bn >= QKV_) && (bn < 2 * QKV_);
    if (ksplit) {
#pragma unroll
        for (int ni = 0; ni < 4; ni++) {
            const int col = bn + wn + ni * 8 + tg * 2;
            const float bx = bias[col], by = bias[col + 1];
            const int colq = col - QKV_;
            const int hh = colq >> 6, dd = colq & 63;
#pragma unroll
            for (int mi = 0; mi < 4; mi++) {
                const int row = bm + wm + mi * 16 + g;
                uint32_t lo0, lo1;
                uint32_t hi0 = splitp(acc[mi][ni][0] + bx, acc[mi][ni][1] + by, lo0);
                uint32_t hi1 = splitp(acc[mi][ni][2] + bx, acc[mi][ni][3] + by, lo1);
#pragma unroll
                for (int rr = 0; rr < 2; rr++) {
                    const int r2 = row + rr * 8;
                    const size_t dst =
                        (size_t)((((r2 >> 11) << 4) + hh) * 16 + ((r2 >> 7) & 15)) * KPIECE
                        + (size_t)(r2 & 127) * AQLD + dd;
                    *(uint32_t*)&kh[dst] = rr ? hi1 : hi0;
                    *(uint32_t*)&kl[dst] = rr ? lo1 : lo0;
                }
            }
        }
    } else {
#pragma unroll
        for (int ni = 0; ni < 4; ni++) {
            const int col = bn + wn + ni * 8 + tg * 2;
            const float bx = bias[col], by = bias[col + 1];
#pragma unroll
            for (int mi = 0; mi < 4; mi++) {
                const int row = bm + wm + mi * 16 + g;
                float2 w0, w1;
                w0.x = acc[mi][ni][0] + bx;
                w0.y = acc[mi][ni][1] + by;
                w1.x = acc[mi][ni][2] + bx;
                w1.y = acc[mi][ni][3] + by;
                *(float2*)&C[(size_t)row * N + col]       = w0;
                *(float2*)&C[(size_t)(row + 8) * N + col] = w1;
            }
        }
    }
}

// ---------------------------------------------------------------------------
// Tensor-core flash attention: bulk-copy K/V pipeline, term-major MMA order
// ---------------------------------------------------------------------------
#define QT_B (128 * AQLD * 2)
#define VT_B (64 * AVLD * 2)
#define OFF_QH 0
#define OFF_QL QT_B
#define OFF_K0 (2 * QT_B)
#define OFF_V0 (2 * QT_B + 4 * QT_B)
#define ATT_SMEM (2 * QT_B + 4 * QT_B + 4 * VT_B + 16)

__global__ __launch_bounds__(256) void attn_tc(
    const float* __restrict__ qkv,
    const bf16* __restrict__ kh_g, const bf16* __restrict__ kl_g,
    const bf16* __restrict__ vh_g, const bf16* __restrict__ vl_g,
    bf16* __restrict__ oh, bf16* __restrict__ ol)
{
    extern __shared__ char smc[];
    const uint32_t sb = smem_u32(smc);
    const uint32_t mbar = sb + (ATT_SMEM - 16);
    bf16* Qh = (bf16*)(smc + OFF_QH);
    bf16* Ql = (bf16*)(smc + OFF_QL);

    const int tid = threadIdx.x;
    const int wid = tid >> 5;
    const int lid = tid & 31;
    const int g   = lid >> 2;
    const int tg  = lid & 3;
    const int qt  = blockIdx.x;
    const int bhx = blockIdx.y;
    const int b   = bhx >> 4;
    const int h   = bhx & 15;
    const int q0  = qt * 128;
    const size_t tok_base = (size_t)b * S_;
    const int hcol = h * D_;
    const int wrow = wid * 16;

    if (tid == 0) {
        MBAR_INIT(mbar, 1);
        MBAR_INIT(mbar + 8, 1);
    }

    // Q load: fp32 -> scaled hi/lo bf16
    {
        const int lr  = tid >> 1;
        const int lch = (tid & 1) * 32;
        const float* qp = qkv + (tok_base + q0 + lr) * (size_t)N_QKV + hcol + lch;
        const int base = lr * AQLD + lch;
#pragma unroll
        for (int j = 0; j < 8; j++) {
            float4 v = *(const float4*)(qp + j * 4);
            v.x *= SCALE; v.y *= SCALE; v.z *= SCALE; v.w *= SCALE;
            uint32_t lo0, lo1;
            uint32_t hi0 = splitp(v.x, v.y, lo0);
            uint32_t hi1 = splitp(v.z, v.w, lo1);
            *(uint32_t*)&Qh[base + j * 4]     = hi0;
            *(uint32_t*)&Qh[base + j * 4 + 2] = hi1;
            *(uint32_t*)&Ql[base + j * 4]     = lo0;
            *(uint32_t*)&Ql[base + j * 4 + 2] = lo1;
        }
    }
    __syncthreads();

    const bf16* pKh = kh_g + (size_t)bhx * 16 * KPIECE;
    const bf16* pKl = kl_g + (size_t)bhx * 16 * KPIECE;
    const bf16* pVh = vh_g + (size_t)bhx * 16 * VPIECE;
    const bf16* pVl = vl_g + (size_t)bhx * 16 * VPIECE;

    auto issue_kv = [&](int buf, int kt) {
        const uint32_t mb  = mbar + buf * 8;
        const uint32_t dkb = sb + OFF_K0 + buf * (2 * QT_B);
        const uint32_t dvb = sb + OFF_V0 + buf * (2 * VT_B);
        MBAR_EXPECT(mb, 2 * QT_B + 2 * VT_B);
        bulkcp(dkb,        pKh + (size_t)kt * KPIECE, QT_B, mb);
        bulkcp(dkb + QT_B, pKl + (size_t)kt * KPIECE, QT_B, mb);
        bulkcp(dvb,        pVh + (size_t)kt * VPIECE, VT_B, mb);
        bulkcp(dvb + VT_B, pVl + (size_t)kt * VPIECE, VT_B, mb);
    };

    if (tid == 0) { issue_kv(0, 0); issue_kv(1, 1); }

    const uint32_t qLane = (uint32_t)((wrow + (lid & 15)) * AQLD + ((lid >> 4) << 3)) * 2;
    const uint32_t kLane = (uint32_t)lid * 144;
    const uint32_t vLane = (uint32_t)lid * 272;

    float acc_o[8][4];
#pragma unroll
    for (int dt = 0; dt < 8; dt++)
#pragma unroll
        for (int r = 0; r < 4; r++) acc_o[dt][r] = 0.f;
    float m0 = -INFINITY, m1 = -INFINITY, l0 = 0.f, l1 = 0.f;

    int ph0 = 0, ph1 = 0;
    const int nkt = S_ / 128;
    for (int kt = 0; kt < nkt; kt++) {
        const int buf = kt & 1;
        if (buf == 0) { MBAR_WAIT(mbar, ph0); ph0 ^= 1; }
        else          { MBAR_WAIT(mbar + 8, ph1); ph1 ^= 1; }

        const uint32_t sKH = sb + OFF_K0 + buf * (2 * QT_B);
        const uint32_t sKL = sKH + QT_B;
        const uint32_t sVH = sb + OFF_V0 + buf * (2 * VT_B);
        const uint32_t sVL = sVH + VT_B;

        // ---- scores (term-major, ntg pairs => distance 8) ----
        float accs[16][4];
#pragma unroll
        for (int nt = 0; nt < 16; nt++)
#pragma unroll
            for (int r = 0; r < 4; r++) accs[nt][r] = 0.f;

#pragma unroll
        for (int ks = 0; ks < 4; ks++) {
            const uint32_t kOff = ks * 32;
            uint32_t ah[4], al[4];
            ldsm4(ah, sb + OFF_QH + qLane + kOff);
            ldsm4(al, sb + OFF_QL + qLane + kOff);
#pragma unroll
            for (int np = 0; np < 2; np++) {
                uint32_t kh0[2][4], kh1[2][4], kl0[2][4], kl1[2][4];
#pragma unroll
                for (int n2 = 0; n2 < 2; n2++) {
                    const uint32_t kAddr =
                        (np * 2 + n2) * (32 * 144) + kLane + kOff;
                    ldsm4(kh0[n2], sKH + kAddr);
                    ldsm4(kh1[n2], sKH + kAddr + 16);
                    ldsm4(kl0[n2], sKL + kAddr);
                    ldsm4(kl1[n2], sKL + kAddr + 16);
                }
#pragma unroll
                for (int n2 = 0; n2 < 2; n2++)
#pragma unroll
                    for (int q = 0; q < 4; q++)
                        mma16816(accs[(np * 2 + n2) * 4 + q], ah[0], ah[1], ah[2], ah[3],
                                 kh0[n2][q], kh1[n2][q]);
#pragma unroll
                for (int n2 = 0; n2 < 2; n2++)
#pragma unroll
                    for (int q = 0; q < 4; q++)
                        mma16816(accs[(np * 2 + n2) * 4 + q], ah[0], ah[1], ah[2], ah[3],
                                 kl0[n2][q], kl1[n2][q]);
#pragma unroll
                for (int n2 = 0; n2 < 2; n2++)
#pragma unroll
                    for (int q = 0; q < 4; q++)
                        mma16816(accs[(np * 2 + n2) * 4 + q], al[0], al[1], al[2], al[3],
                                 kh0[n2][q], kh1[n2][q]);
            }
        }

        // ---- online softmax ----
        float nm0 = m0, nm1 = m1;
#pragma unroll
        for (int nt = 0; nt < 16; nt++) {
            nm0 = fmaxf(nm0, fmaxf(accs[nt][0], accs[nt][1]));
            nm1 = fmaxf(nm1, fmaxf(accs[nt][2], accs[nt][3]));
        }
        nm0 = fmaxf(nm0, __shfl_xor_sync(0xffffffffu, nm0, 1));
        nm0 = fmaxf(nm0, __shfl_xor_sync(0xffffffffu, nm0, 2));
        nm1 = fmaxf(nm1, __shfl_xor_sync(0xffffffffu, nm1, 1));
        nm1 = fmaxf(nm1, __shfl_xor_sync(0xffffffffu, nm1, 2));
        const float corr0 = __expf(m0 - nm0);
        const float corr1 = __expf(m1 - nm1);
        float rs0 = 0.f, rs1 = 0.f;
#pragma unroll
        for (int nt = 0; nt < 16; nt++) {
            accs[nt][0] = __expf(accs[nt][0] - nm0);
            accs[nt][1] = __expf(accs[nt][1] - nm0);
            accs[nt][2] = __expf(accs[nt][2] - nm1);
            accs[nt][3] = __expf(accs[nt][3] - nm1);
            rs0 += accs[nt][0] + accs[nt][1];
            rs1 += accs[nt][2] + accs[nt][3];
        }
        rs0 += __shfl_xor_sync(0xffffffffu, rs0, 1);
        rs0 += __shfl_xor_sync(0xffffffffu, rs0, 2);
        rs1 += __shfl_xor_sync(0xffffffffu, rs1, 1);
        rs1 += __shfl_xor_sync(0xffffffffu, rs1, 2);
        l0 = l0 * corr0 + rs0;
        l1 = l1 * corr1 + rs1;
        m0 = nm0; m1 = nm1;
#pragma unroll
        for (int dt = 0; dt < 8; dt++) {
            acc_o[dt][0] *= corr0;
            acc_o[dt][1] *= corr0;
            acc_o[dt][2] *= corr1;
            acc_o[dt][3] *= corr1;
        }

        // ---- PV (term-major across both dtg => distance 8) ----
#pragma unroll
        for (int kc = 0; kc < 8; kc++) {
            uint32_t pah[4], pal[4];
            pah[0] = splitp(accs[2 * kc][0],     accs[2 * kc][1],     pal[0]);
            pah[1] = splitp(accs[2 * kc][2],     accs[2 * kc][3],     pal[1]);
            pah[2] = splitp(accs[2 * kc + 1][0], accs[2 * kc + 1][1], pal[2]);
            pah[3] = splitp(accs[2 * kc + 1][2], accs[2 * kc + 1][3], pal[3]);
            const uint32_t vOff = kc * 32;
            uint32_t vh0[2][4], vh1[2][4], vl0[2][4], vl1[2][4];
#pragma unroll
            for (int d2 = 0; d2 < 2; d2++) {
                const uint32_t vAddr = d2 * (32 * 272) + vLane + vOff;
                ldsm4(vh0[d2], sVH + vAddr);
                ldsm4(vh1[d2], sVH + vAddr + 16);
                ldsm4(vl0[d2], sVL + vAddr);
                ldsm4(vl1[d2], sVL + vAddr + 16);
            }
#pragma unroll
            for (int d2 = 0; d2 < 2; d2++)
#pragma unroll
                for (int q = 0; q < 4; q++)
                    mma16816(acc_o[d2 * 4 + q], pah[0], pah[1], pah[2], pah[3],
                             vh0[d2][q], vh1[d2][q]);
#pragma unroll
            for (int d2 = 0; d2 < 2; d2++)
#pragma unroll
                for (int q = 0; q < 4; q++)
                    mma16816(acc_o[d2 * 4 + q], pah[0], pah[1], pah[2], pah[3],
                             vl0[d2][q], vl1[d2][q]);
#pragma unroll
            for (int d2 = 0; d2 < 2; d2++)
#pragma unroll
                for (int q = 0; q < 4; q++)
                    mma16816(acc_o[d2 * 4 + q], pal[0], pal[1], pal[2], pal[3],
                             vh0[d2][q], vh1[d2][q]);
        }
        __syncthreads();
        if (tid == 0 && kt + 2 < nkt) issue_kv(buf, kt + 2);
    }

    // ---- epilogue: write tiled split bf16 output ----
    const float inv0 = 1.f / l0;
    const float inv1 = 1.f / l1;
    const int row0 = (int)(tok_base + q0 + wrow + g);
#pragma unroll
    for (int dt = 0; dt < 8; dt++) {
        const int col = hcol + dt * 8 + tg * 2;
        uint32_t lo0, lo1;
        uint32_t hi0 = splitp(acc_o[dt][0] * inv0, acc_o[dt][1] * inv0, lo0);
        uint32_t hi1 = splitp(acc_o[dt][2] * inv1, acc_o[dt][3] * inv1, lo1);
#pragma unroll
        for (int rr = 0; rr < 2; rr++) {
            const int r2 = row0 + rr * 8;
            const size_t dst = ((size_t)((r2 >> 7) * 32 + (col >> 5))) * APIECE
                             + (size_t)(r2 & 127) * GLD2 + (col & 31);
            *(uint32_t*)&oh[dst] = rr ? hi1 : hi0;
            *(uint32_t*)&ol[dst] = rr ? lo1 : lo0;
        }
    }
}

// ---------------------------------------------------------------------------
extern "C" void kernel_launch(void* const* d_in, const int* in_sizes, int n_in,
                              void* d_out, int out_size)
{
    const float* x     = (const float*)d_in[0];
    const float* w_qkv = (const float*)d_in[1];
    const float* b_qkv = (const float*)d_in[2];
    const float* w_o   = (const float*)d_in[3];
    const float* b_o   = (const float*)d_in[4];
    float* out = (float*)d_out;

    float *p_qkv;
    bf16 *p_xh, *p_xl, *p_wqh, *p_wql, *p_woh, *p_wol;
    bf16 *p_ath, *p_atl, *p_kh, *p_kl, *p_vh, *p_vl;
    cudaGetSymbolAddress((void**)&p_qkv, g_qkv);
    cudaGetSymbolAddress((void**)&p_xh, g_xh);
    cudaGetSymbolAddress((void**)&p_xl, g_xl);
    cudaGetSymbolAddress((void**)&p_wqh, g_wqh);
    cudaGetSymbolAddress((void**)&p_wql, g_wql);
    cudaGetSymbolAddress((void**)&p_woh, g_woh);
    cudaGetSymbolAddress((void**)&p_wol, g_wol);
    cudaGetSymbolAddress((void**)&p_ath, g_ath);
    cudaGetSymbolAddress((void**)&p_atl, g_atl);
    cudaGetSymbolAddress((void**)&p_kh, g_kh);
    cudaGetSymbolAddress((void**)&p_kl, g_kl);
    cudaGetSymbolAddress((void**)&p_vh, g_vh);
    cudaGetSymbolAddress((void**)&p_vl, g_vl);

    cudaFuncSetAttribute(gemm_bf, cudaFuncAttributeMaxDynamicSharedMemorySize,
                         GEMM_SMEM);
    cudaFuncSetAttribute(attn_tc, cudaFuncAttributeMaxDynamicSharedMemorySize,
                         ATT_SMEM);

    split_tiled<<<(M_TOK * HID) / 2048, 256>>>(x, p_xh, p_xl, HID);
    split_tiled<<<(N_QKV * HID) / 2048, 256>>>(w_qkv, p_wqh, p_wql, HID);
    split_tiled<<<(HID * QKV_) / 2048, 256>>>(w_o, p_woh, p_wol, QKV_);

    // 1) QKV projection (K columns emitted pre-split tiled)
    {
        dim3 grid(N_QKV / 128, M_TOK / 128);
        gemm_bf<<<grid, 256, GEMM_SMEM>>>(p_xh, p_xl, p_wqh, p_wql, b_qkv, p_qkv,
                                          p_kh, p_kl, M_TOK, N_QKV, HID, 1);
    }
    // V transpose+split (tiled)
    {
        dim3 grid(S_ / 64, B_ * H_);
        split_vt<<<grid, 256>>>(p_qkv, p_vh, p_vl);
    }
    // 2) attention (emits tiled split output)
    {
        dim3 grid(S_ / 128, B_ * H_);
        attn_tc<<<grid, 256, ATT_SMEM>>>(p_qkv, p_kh, p_kl, p_vh, p_vl, p_ath, p_atl);
    }
    // 3) output projection
    {
        dim3 grid(QKV_ / 128, M_TOK / 128);
        gemm_bf<<<grid, 256, GEMM_SMEM>>>(p_ath, p_atl, p_woh, p_wol, b_o, out,
                                          nullptr, nullptr, M_TOK, QKV_, HID, 0);
    }
}